// round 17
// baseline (speedup 1.0000x reference)
#include <cuda_runtime.h>
#include <cuda_fp16.h>
#include <cstdint>
#include <math.h>

#define CD 256
#define MD 512
#define HWD 4096
#define NIMG 16
#define LAMBDA 0.0025f
#define SROW 514

// SMEM layout (bytes)
#define XA_HI  65792u      // x-hat hi [32 x 528B]; later att hi [32 x 1040B]
#define ATT_HI 65792u
#define RED_O  99584u      // 256 f32
#define INV_O  100608u     // 32 f32
#define SMEM_SZ 100736u

// Fragment-major B operands (fp16 hi-only): one warp LDG = 32 contiguous lanes.
__device__ uint2 g_B1f[32768];   // [(mtile*16+kt)*32+lane] hi pairs (c-pairs)
__device__ uint2 g_B2f[32768];   // [(ctile*32+kt)*32+lane] {hi(p0), hi(p1)}
__device__ __half g_Mh[MD*CD];

__device__ __forceinline__ uint32_t smem_u32(const void* p) {
    uint32_t a;
    asm("{ .reg .u64 t; cvta.to.shared.u64 t, %1; cvt.u32.u64 %0, t; }" : "=r"(a) : "l"(p));
    return a;
}
#define LDSM4(r,a) asm volatile("ldmatrix.sync.aligned.m8n8.x4.shared.b16 {%0,%1,%2,%3},[%4];" \
    : "=r"((r)[0]),"=r"((r)[1]),"=r"((r)[2]),"=r"((r)[3]) : "r"(a))
#define MMA(d,a,bb) asm volatile( \
    "mma.sync.aligned.m16n8k16.row.col.f32.f16.f16.f32 {%0,%1,%2,%3},{%4,%5,%6,%7},{%8,%9},{%0,%1,%2,%3};" \
    : "+f"((d)[0]),"+f"((d)[1]),"+f"((d)[2]),"+f"((d)[3]) \
    : "r"((a)[0]),"r"((a)[1]),"r"((a)[2]),"r"((a)[3]),"r"((bb)[0]),"r"((bb)[1]))

__device__ __forceinline__ void pack_h(const float* v, char* hi) {
    uint4 h;
    __half2 h0 = __floats2half2_rn(v[0], v[1]), h1 = __floats2half2_rn(v[2], v[3]);
    __half2 h2 = __floats2half2_rn(v[4], v[5]), h3 = __floats2half2_rn(v[6], v[7]);
    h.x = *(uint32_t*)&h0; h.y = *(uint32_t*)&h1; h.z = *(uint32_t*)&h2; h.w = *(uint32_t*)&h3;
    *(uint4*)hi = h;
}

// ------- prologue: MLP, 4 slots/block, 128 blocks, 512 threads (weight traffic /4) -------
__global__ __launch_bounds__(512)
void mem_mlp_kernel(const float* __restrict__ memory,
                    const float* __restrict__ w1, const float* __restrict__ b1,
                    const float* __restrict__ w2, const float* __restrict__ b2) {
    __shared__ float srow[4][CD];
    __shared__ float part[4][128][4];     // [qr][u][s]; later reused as v[s][c]
    __shared__ float h[4][128];
    __shared__ float part2[2][256][4];    // [hf][c][s]
    __shared__ float scr[4][256];
    __shared__ float invs[4];
    __shared__ __half sh[4][CD];
    const int m0 = blockIdx.x*4, tid = threadIdx.x;

    for (int i = tid; i < 4*CD; i += 512)
        srow[i >> 8][i & 255] = memory[(m0 + (i >> 8))*CD + (i & 255)];
    __syncthreads();

    {   // layer1: (u, quarter qr), 4 slots per thread
        const int u = tid & 127, qr = tid >> 7;
        float a0 = 0.f, a1 = 0.f, a2 = 0.f, a3 = 0.f;
        const int c0 = qr*64;
#pragma unroll 16
        for (int c = c0; c < c0 + 64; c++) {
            const float wv = w1[c*128 + u];
            a0 += srow[0][c]*wv; a1 += srow[1][c]*wv;
            a2 += srow[2][c]*wv; a3 += srow[3][c]*wv;
        }
        part[qr][u][0] = a0; part[qr][u][1] = a1;
        part[qr][u][2] = a2; part[qr][u][3] = a3;
    }
    __syncthreads();
    {   // combine into h: (s, u)
        const int u = tid & 127, s = tid >> 7;
        h[s][u] = fmaxf(b1[u] + part[0][u][s] + part[1][u][s]
                               + part[2][u][s] + part[3][u][s], 0.f);
    }
    __syncthreads();
    {   // layer2: (c, half hf), 4 slots per thread
        const int c = tid & 255, hf = tid >> 8;
        float a0 = 0.f, a1 = 0.f, a2 = 0.f, a3 = 0.f;
        const int j0 = hf*64;
#pragma unroll 16
        for (int j = j0; j < j0 + 64; j++) {
            const float wv = w2[j*CD + c];
            a0 += h[0][j]*wv; a1 += h[1][j]*wv;
            a2 += h[2][j]*wv; a3 += h[3][j]*wv;
        }
        part2[hf][c][0] = a0; part2[hf][c][1] = a1;
        part2[hf][c][2] = a2; part2[hf][c][3] = a3;
    }
    __syncthreads();
    {   // finalize 2 slots per thread (c, g)
        const int c = tid & 255, g = tid >> 8;
        const float bb = b2[c];
        float v0 = fmaxf(bb + part2[0][c][2*g]   + part2[1][c][2*g],   0.f);
        float v1 = fmaxf(bb + part2[0][c][2*g+1] + part2[1][c][2*g+1], 0.f);
        scr[2*g][c] = v0*v0;  scr[2*g+1][c] = v1*v1;
        ((float*)part)[(2*g)*256 + c]   = v0;   // part is dead, reuse
        ((float*)part)[(2*g+1)*256 + c] = v1;
    }
    __syncthreads();
    if (tid < 128) {   // 4 warps reduce 4 slots
        const int s = tid >> 5, l = tid & 31;
        float ss = 0.f;
#pragma unroll
        for (int k = 0; k < 8; k++) ss += scr[s][l + 32*k];
#pragma unroll
        for (int o = 16; o > 0; o >>= 1) ss += __shfl_xor_sync(0xffffffffu, ss, o);
        if (l == 0) invs[s] = 1.f / fmaxf(sqrtf(ss), 1e-12f);
    }
    __syncthreads();
    {   // normalize + store: (c, g) -> 2 slots
        const int c = tid & 255, g = tid >> 8;
#pragma unroll
        for (int ds = 0; ds < 2; ds++) {
            const int s = 2*g + ds;
            const float v = ((float*)part)[s*256 + c] * invs[s];
            const __half hb = __float2half_rn(v);
            g_Mh[(m0+s)*CD + c] = hb;
            sh[s][c] = hb;
        }
    }
    __syncthreads();
    if (tid < 256) {   // B1f: 4 slots x 64 words
        const int s = tid >> 6, w = tid & 63;
        const int kt = w >> 2, q = w & 3;
        const int c0 = kt*16 + 2*q;
        const int m = m0 + s;
        __half2 hh0, hh1;
        hh0.x = sh[s][c0];     hh0.y = sh[s][c0+1];
        hh1.x = sh[s][c0+8];   hh1.y = sh[s][c0+9];
        g_B1f[((m >> 3)*16 + kt)*32 + (m & 7)*4 + q] =
            make_uint2(*(uint32_t*)&hh0, *(uint32_t*)&hh1);
    }
}

// B2f pack: flat idx == output index (ct*1024 + kt*32 + lane)
__global__ void pack2_kernel() {
    const int idx = blockIdx.x*256 + threadIdx.x;   // 32768
    const int lane = idx & 31, kt = (idx >> 5) & 31, ct = idx >> 10;
    const int c = ct*8 + (lane >> 2), q = lane & 3;
    const int p0 = kt*8 + q, p1 = p0 + 4;
    __half2 hh0, hh1;
    hh0.x = g_Mh[(2*p0)*CD + c];   hh0.y = g_Mh[(2*p0+1)*CD + c];
    hh1.x = g_Mh[(2*p1)*CD + c];   hh1.y = g_Mh[(2*p1+1)*CD + c];
    g_B2f[idx] = make_uint2(*(uint32_t*)&hh0, *(uint32_t*)&hh1);
}

// ---------------- fused HMMA kernel: 32 tok/CTA, 2 CTA/SM, fp16 hi-only ----------------
__global__ __launch_bounds__(256, 2)
void fused_kernel(const float* __restrict__ x, float* __restrict__ out,
                  float* __restrict__ attmap) {
    extern __shared__ char smem[];
    float* sc  = (float*)smem;
    float* red = (float*)(smem + RED_O);
    float* inv = (float*)(smem + INV_O);
    const uint32_t sb = smem_u32(smem);
    const int tid = threadIdx.x, lane = tid & 31, wid = tid >> 5;
    const int b = blockIdx.x;
    const int n = b >> 7;
    const int hw0 = (b & 127) << 5;
    const float* xb = x + (size_t)n*CD*HWD + hw0;

    // ---- stage x tile [256 c][32 t], float4 loads ----
    for (int i = tid; i < CD*8; i += 256) {
        const int c = i >> 3, tq = (i & 7)*4;
        *(float4*)&sc[c*32 + tq] = *(const float4*)&xb[(size_t)c*HWD + tq];
    }
    __syncthreads();

    // ---- token L2 norms ----
    {
        const int t = tid & 31, p = tid >> 5;
        float s = 0.f;
        for (int c = p*32; c < p*32 + 32; c++) { float v = sc[c*32 + t]; s += v*v; }
        red[p*32 + t] = s;
    }
    __syncthreads();
    if (tid < 32) {
        float s = 0.f;
        for (int p = 0; p < 8; p++) s += red[p*32 + tid];
        inv[tid] = 1.f / fmaxf(sqrtf(s), 1e-12f);
    }
    __syncthreads();

    // ---- pack x-hat hi tile [32 t][256 c], rows 528B (fp16 hi only) ----
    for (int i = tid; i < 1024; i += 256) {
        const int t = i >> 5, ch = i & 31;
        const float iv = inv[t];
        float v[8];
#pragma unroll
        for (int j = 0; j < 8; j++) v[j] = sc[(ch*8 + j)*32 + t] * iv;
        pack_h(v, smem + XA_HI + t*528 + ch*16);
    }
    __syncthreads();

    // ---- GEMM1: warp = 32 tok x 64 m, K=256, fp16 hi-only ----
    {
        const int mg = wid;
        float acc[2][8][4] = {};
        const uint32_t a0 = sb + XA_HI + (lane & 15)*528 + (lane >> 4)*16;
        const uint32_t a1 = a0 + 16*528;
        const uint2* b1p = g_B1f + (size_t)mg*8*512 + lane;
        uint2 qa[4], qb[4];
        uint32_t ah0[4], ah1[4];

#define G1LOAD(q, kt, JJ) { _Pragma("unroll") for (int j = 0; j < 4; j++) \
        (q)[j] = b1p[(size_t)((JJ)*4 + j)*512 + (kt)*32]; }
#define G1MMA(q, JJ) { _Pragma("unroll") for (int j = 0; j < 4; j++) { \
        uint32_t bh[2] = {(q)[j].x, (q)[j].y}; \
        MMA(acc[0][(JJ)*4+j], ah0, bh); MMA(acc[1][(JJ)*4+j], ah1, bh); } }

        G1LOAD(qa, 0, 0);
        for (int kt = 0; kt < 16; kt++) {
            LDSM4(ah0, a0 + kt*32);
            LDSM4(ah1, a1 + kt*32);
            G1LOAD(qb, kt, 1);
            G1MMA(qa, 0);
            if (kt < 15) G1LOAD(qa, kt+1, 0);
            G1MMA(qb, 1);
        }
#pragma unroll
        for (int th = 0; th < 2; th++)
#pragma unroll
            for (int j = 0; j < 8; j++) {
                const int r0 = th*16 + (lane >> 2);
                const int c = mg*64 + j*8 + (lane & 3)*2;
                *(float2*)&sc[r0*SROW + c]     = make_float2(acc[th][j][0], acc[th][j][1]);
                *(float2*)&sc[(r0+8)*SROW + c] = make_float2(acc[th][j][2], acc[th][j][3]);
            }
    }
    __syncthreads();

    // ---- softmax + shrink + L1 renorm (warp -> 4 tokens) ----
    for (int rt = 0; rt < 4; rt++) {
        const int t = wid*4 + rt;
        float* row = sc + t*SROW;
        float e[16], s = 0.f;
#pragma unroll
        for (int k = 0; k < 16; k++) { e[k] = __expf(row[lane + 32*k]); s += e[k]; }
#pragma unroll
        for (int o = 16; o > 0; o >>= 1) s += __shfl_xor_sync(0xffffffffu, s, o);
        const float invs = 1.f / s;
        float as = 0.f;
#pragma unroll
        for (int k = 0; k < 16; k++) { e[k] = fmaxf(e[k]*invs - LAMBDA, 0.f); as += e[k]; }
#pragma unroll
        for (int o = 16; o > 0; o >>= 1) as += __shfl_xor_sync(0xffffffffu, as, o);
        const float inva = 1.f / fmaxf(as, 1e-12f);
#pragma unroll
        for (int k = 0; k < 16; k++) row[lane + 32*k] = e[k] * inva;
    }
    __syncthreads();

    // ---- attmap write (float4 along t) ----
    float* amb = attmap + (size_t)n*MD*HWD + hw0;
    for (int i = tid; i < MD*8; i += 256) {
        const int m = i >> 3, tq = (i & 7)*4;
        float4 v = make_float4(sc[tq*SROW + m], sc[(tq+1)*SROW + m],
                               sc[(tq+2)*SROW + m], sc[(tq+3)*SROW + m]);
        *(float4*)&amb[(size_t)m*HWD + tq] = v;
    }
    // reg-staged att pack (fp16 hi only): thread -> row pt, col block pg
    {
        const int pt = tid & 31, pg = (tid >> 5) * 64;
        float rbuf[64];
#pragma unroll
        for (int j = 0; j < 32; j++)
            *(float2*)&rbuf[2*j] = *(float2*)&sc[pt*SROW + pg + 2*j];
        __syncthreads();
        char* hb = smem + ATT_HI + pt*1040 + pg*2;
#pragma unroll
        for (int jg = 0; jg < 8; jg++)
            pack_h(rbuf + jg*8, hb + jg*16);
    }
    __syncthreads();

    // ---- GEMM2: warp = 32 tok x 32 c, K=512, fp16 hi x hi ----
    float acc2[2][4][4] = {};
    {
        const int cg = wid;
        const uint2* b2p = g_B2f + (size_t)cg*4096 + lane;
        uint2 qa2[2], qb2[2];
        uint32_t ah[2][4];
        const uint32_t ha0 = sb + ATT_HI + (lane & 15)*1040 + (lane >> 4)*16;

#define G2LOAD(q, kt, JJ) { _Pragma("unroll") for (int j = 0; j < 2; j++) \
        (q)[j] = b2p[(size_t)((JJ)*2 + j)*1024 + (kt)*32]; }
#define G2MMA(q, JJ) { _Pragma("unroll") for (int j = 0; j < 2; j++) { \
        uint32_t bh[2] = {(q)[j].x, (q)[j].y}; \
        MMA(acc2[0][(JJ)*2+j], ah[0], bh); \
        MMA(acc2[1][(JJ)*2+j], ah[1], bh); } }

        G2LOAD(qa2, 0, 0);
        for (int kt = 0; kt < 32; kt++) {
            LDSM4(ah[0], ha0 + kt*32);
            LDSM4(ah[1], ha0 + 16*1040 + kt*32);
            G2LOAD(qb2, kt, 1);
            G2MMA(qa2, 0);
            if (kt < 31) G2LOAD(qa2, kt+1, 0);
            G2MMA(qb2, 1);
        }
    }
    __syncthreads();   // all warps done reading att tiles

    // ---- stage out [32 t][260], then float4 write along t ----
    {
        const int cg = wid;
#pragma unroll
        for (int th = 0; th < 2; th++)
#pragma unroll
            for (int j = 0; j < 4; j++) {
                const int r0 = th*16 + (lane >> 2);
                const int c = cg*32 + j*8 + (lane & 3)*2;
                *(float2*)&sc[r0*260 + c]     = make_float2(acc2[th][j][0], acc2[th][j][1]);
                *(float2*)&sc[(r0+8)*260 + c] = make_float2(acc2[th][j][2], acc2[th][j][3]);
            }
    }
    __syncthreads();
    float* ob = out + (size_t)n*CD*HWD + hw0;
    for (int i = tid; i < CD*8; i += 256) {
        const int c = i >> 3, tq = (i & 7)*4;
        float4 v = make_float4(sc[tq*260 + c], sc[(tq+1)*260 + c],
                               sc[(tq+2)*260 + c], sc[(tq+3)*260 + c]);
        *(float4*)&ob[(size_t)c*HWD + tq] = v;
    }
}

// ---------------------------------------------------------------------------
extern "C" void kernel_launch(void* const* d_in, const int* in_sizes, int n_in,
                              void* d_out, int out_size) {
    const float* x      = (const float*)d_in[0];
    const float* memory = (const float*)d_in[1];
    const float* w1     = (const float*)d_in[2];
    const float* b1     = (const float*)d_in[3];
    const float* w2     = (const float*)d_in[4];
    const float* b2     = (const float*)d_in[5];

    float* out    = (float*)d_out;
    float* attmap = out + (size_t)NIMG*CD*HWD;

    mem_mlp_kernel<<<128, 512>>>(memory, w1, b1, w2, b2);
    pack2_kernel<<<128, 256>>>();

    cudaFuncSetAttribute(fused_kernel, cudaFuncAttributeMaxDynamicSharedMemorySize, SMEM_SZ);
    fused_kernel<<<1024, 256, SMEM_SZ>>>(x, out, attmap);
}